// round 15
// baseline (speedup 1.0000x reference)
#include <cuda_runtime.h>
#include <cuda_fp16.h>
#include <math.h>

#define D 64
#define NF 3
#define MAXU 100000
#define MAXENT 200000
#define MAXE 500000

typedef unsigned long long ull;

// ---------------- scratch (device globals) ----------------
__device__ __align__(256) float g_tabf[(size_t)(MAXU + MAXENT) * D];          // Pu, Pi (fp32)
__device__ __align__(256) __half g_tabh[(size_t)(MAXU + MAXENT) * 2 * D];     // Qu, Qi, ue16, ie16
__device__ __align__(256) __half g_rel[(size_t)MAXE * D];                     // per-edge rel_ui
__device__ __align__(256) __half g_mean[(size_t)(MAXU * NF + MAXENT) * D];    // s1m16, ysm16
__device__ __align__(256) float g_acc[(size_t)MAXU * NF * D * 2 + (size_t)MAXENT * D * 2
                                      + (size_t)MAXU * NF + MAXENT];
__device__ __align__(256) unsigned char g_rtype[MAXE];

// ---------------- helpers ----------------
__device__ __forceinline__ ull pk2(float a, float b) {
    ull r; asm("mov.b64 %0, {%1, %2};" : "=l"(r) : "f"(a), "f"(b)); return r;
}
__device__ __forceinline__ void fma2(ull& d, ull a, ull b) {
    asm("fma.rn.f32x2 %0, %1, %2, %0;" : "+l"(d) : "l"(a), "l"(b));
}
__device__ __forceinline__ float2 upk2(ull v) {
    float2 f; asm("mov.b64 {%0, %1}, %2;" : "=f"(f.x), "=f"(f.y) : "l"(v)); return f;
}
__device__ __forceinline__ float lrelu(float x) { return x > 0.f ? x : 0.01f * x; }

__device__ __forceinline__ float hsum16(float v) {
    v += __shfl_xor_sync(0xffffffffu, v, 8);
    v += __shfl_xor_sync(0xffffffffu, v, 4);
    v += __shfl_xor_sync(0xffffffffu, v, 2);
    v += __shfl_xor_sync(0xffffffffu, v, 1);
    return v;
}
__device__ __forceinline__ float hsum8(float v) {
    v += __shfl_xor_sync(0xffffffffu, v, 4);
    v += __shfl_xor_sync(0xffffffffu, v, 2);
    v += __shfl_xor_sync(0xffffffffu, v, 1);
    return v;
}

struct F8 { float4 a, b; };

__device__ __forceinline__ float4 h4_to_f4(uint2 raw) {
    __half2 x = *(__half2*)&raw.x;
    __half2 y = *(__half2*)&raw.y;
    float2 fx = __half22float2(x), fy = __half22float2(y);
    return make_float4(fx.x, fx.y, fy.x, fy.y);
}
__device__ __forceinline__ F8 u4_to_f8(uint4 raw) {
    F8 r;
    r.a = h4_to_f4(make_uint2(raw.x, raw.y));
    r.b = h4_to_f4(make_uint2(raw.z, raw.w));
    return r;
}
__device__ __forceinline__ F8 ldh8(const __half* p)    { return u4_to_f8(*(const uint4*)p); }
__device__ __forceinline__ F8 ldh8_cs(const __half* p) { return u4_to_f8(__ldcs((const uint4*)p)); }

__device__ __forceinline__ float4 ldh4(const __half* p) { return h4_to_f4(*(const uint2*)p); }
__device__ __forceinline__ uint2 f4_to_h4(float4 v) {
    __half2 h0 = __floats2half2_rn(v.x, v.y);
    __half2 h1 = __floats2half2_rn(v.z, v.w);
    uint2 raw;
    raw.x = *(unsigned int*)&h0;
    raw.y = *(unsigned int*)&h1;
    return raw;
}
__device__ __forceinline__ void sth4(__half* p, float4 v)    { *(uint2*)p = f4_to_h4(v); }
__device__ __forceinline__ void sth4_cs(__half* p, float4 v) { __stcs((uint2*)p, f4_to_h4(v)); }

__device__ __forceinline__ void red4(float* p, float4 v) {
    asm volatile("red.global.add.v4.f32 [%0], {%1, %2, %3, %4};"
                 :: "l"(p), "f"(v.x), "f"(v.y), "f"(v.z), "f"(v.w) : "memory");
}
__device__ __forceinline__ void red8(float* p, F8 v) {
    red4(p, v.a);
    red4(p + 4, v.b);
}
__device__ __forceinline__ F8 scale8(F8 v, float s) {
    F8 r;
    r.a = make_float4(s * v.a.x, s * v.a.y, s * v.a.z, s * v.a.w);
    r.b = make_float4(s * v.b.x, s * v.b.y, s * v.b.z, s * v.b.w);
    return r;
}
__device__ __forceinline__ float dot8(F8 x, F8 y) {
    return x.a.x * y.a.x + x.a.y * y.a.y + x.a.z * y.a.z + x.a.w * y.a.w
         + x.b.x * y.b.x + x.b.y * y.b.y + x.b.z * y.b.z + x.b.w * y.b.w;
}

// ---------------- K0: fused per-source precompute ----------------
__global__ __launch_bounds__(256) void precompute2(
    const float* __restrict__ user_emb, const float* __restrict__ entity_emb,
    const float* __restrict__ WW_w, const float* __restrict__ WWi_w,
    float* __restrict__ Pu, float* __restrict__ Pi,
    __half* __restrict__ Qu, __half* __restrict__ Qi,
    __half* __restrict__ ue16, __half* __restrict__ ie16,
    int U, int ENT)
{
    const int role = blockIdx.y;   // 0 = user, 1 = entity
    const float* src; float* Pdst; __half* Qdst; __half* cp; int rows;
    int colA, colB;
    if (role == 0) { src = user_emb;   Pdst = Pu; Qdst = Qu; cp = ue16; rows = U;
                     colA = 0;  colB = D; }
    else           { src = entity_emb; Pdst = Pi; Qdst = Qi; cp = ie16; rows = ENT;
                     colA = D;  colB = 0; }

    __shared__ float wA[D * D];   // wA[k*64 + d] = WW_w [d][colA + k]
    __shared__ float wB[D * D];   // wB[k*64 + d] = WWi_w[d][colB + k]
    for (int idx = threadIdx.x; idx < D * D; idx += 256) {
        int d = idx >> 6, k = idx & 63;
        wA[k * D + d] = WW_w [d * 2 * D + colA + k];
        wB[k * D + d] = WWi_w[d * 2 * D + colB + k];
    }
    __syncthreads();

    const int hw  = blockIdx.x * 16 + (threadIdx.x >> 4);
    const int nhw = gridDim.x * 16;
    const int l16 = threadIdx.x & 15;
    const int d0  = l16 * 4;

    for (int r = hw; r < rows; r += nhw) {
        float4 x = *(const float4*)(src + (size_t)r * D + d0);
        sth4(cp + (size_t)r * D + d0, x);

        ull aA01 = pk2(0.f, 0.f), aA23 = pk2(0.f, 0.f);
        ull aB01 = pk2(0.f, 0.f), aB23 = pk2(0.f, 0.f);

        #pragma unroll
        for (int j = 0; j < 16; j++) {
            float bx = __shfl_sync(0xffffffffu, x.x, j, 16);
            float by = __shfl_sync(0xffffffffu, x.y, j, 16);
            float bz = __shfl_sync(0xffffffffu, x.z, j, 16);
            float bw = __shfl_sync(0xffffffffu, x.w, j, 16);
            float xv[4] = {bx, by, bz, bw};
            #pragma unroll
            for (int kk = 0; kk < 4; kk++) {
                int k = j * 4 + kk;
                float4 wa = *(const float4*)&wA[k * D + d0];
                float4 wb = *(const float4*)&wB[k * D + d0];
                ull xp = pk2(xv[kk], xv[kk]);
                fma2(aA01, pk2(wa.x, wa.y), xp);
                fma2(aA23, pk2(wa.z, wa.w), xp);
                fma2(aB01, pk2(wb.x, wb.y), xp);
                fma2(aB23, pk2(wb.z, wb.w), xp);
            }
        }

        float2 A01 = upk2(aA01), A23 = upk2(aA23);
        *(float4*)(Pdst + (size_t)r * D + d0)
            = make_float4(A01.x, A01.y, A23.x, A23.y);
        float2 B01 = upk2(aB01), B23 = upk2(aB23);
        sth4(Qdst + (size_t)r * D + d0,
             make_float4(B01.x, B01.y, B23.x, B23.y));
    }
}

// ---------------- route1: routing (16-lane; fp32 gathers already max width) --------
__global__ __launch_bounds__(256) void route1(
    const int* __restrict__ uidx, const int* __restrict__ iidx,
    const float* __restrict__ WW_b, const float* __restrict__ latent,
    const float* __restrict__ Pu, const float* __restrict__ Pi,
    float* __restrict__ cnt, float* __restrict__ cnti,
    __half* __restrict__ rel_e, unsigned char* __restrict__ rtype, int E)
{
    int p = (blockIdx.x * blockDim.x + threadIdx.x) >> 4;
    int l16 = threadIdx.x & 15;
    int np = (gridDim.x * blockDim.x) >> 4;
    int d0 = l16 * 4;

    float4 bb = *(const float4*)(WW_b + d0);
    float4 l0 = *(const float4*)(latent + 0 * D + d0);
    float4 l1 = *(const float4*)(latent + 1 * D + d0);
    float4 l2 = *(const float4*)(latent + 2 * D + d0);

    for (int e0 = p * 2; e0 < E; e0 += np * 2) {
        int e1 = e0 + 1;
        bool has1 = (e1 < E);
        int u0 = __ldcs(uidx + e0), i0 = __ldcs(iidx + e0);
        int u1 = has1 ? __ldcs(uidx + e1) : u0;
        int i1 = has1 ? __ldcs(iidx + e1) : i0;

        float4 pu0 = *(const float4*)(Pu + (size_t)u0 * D + d0);
        float4 pi0 = *(const float4*)(Pi + (size_t)i0 * D + d0);
        float4 pu1 = *(const float4*)(Pu + (size_t)u1 * D + d0);
        float4 pi1 = *(const float4*)(Pi + (size_t)i1 * D + d0);

        float4 r0;
        r0.x = lrelu(pu0.x + pi0.x + bb.x);
        r0.y = lrelu(pu0.y + pi0.y + bb.y);
        r0.z = lrelu(pu0.z + pi0.z + bb.z);
        r0.w = lrelu(pu0.w + pi0.w + bb.w);
        float a0 = hsum16(r0.x * l0.x + r0.y * l0.y + r0.z * l0.z + r0.w * l0.w);
        float a1 = hsum16(r0.x * l1.x + r0.y * l1.y + r0.z * l1.z + r0.w * l1.w);
        float a2 = hsum16(r0.x * l2.x + r0.y * l2.y + r0.z * l2.z + r0.w * l2.w);
        int t0 = 0; float best0 = a0;
        if (a1 > best0) { best0 = a1; t0 = 1; }
        if (a2 > best0) { best0 = a2; t0 = 2; }

        float4 r1;
        r1.x = lrelu(pu1.x + pi1.x + bb.x);
        r1.y = lrelu(pu1.y + pi1.y + bb.y);
        r1.z = lrelu(pu1.z + pi1.z + bb.z);
        r1.w = lrelu(pu1.w + pi1.w + bb.w);
        float b0 = hsum16(r1.x * l0.x + r1.y * l0.y + r1.z * l0.z + r1.w * l0.w);
        float b1 = hsum16(r1.x * l1.x + r1.y * l1.y + r1.z * l1.z + r1.w * l1.w);
        float b2 = hsum16(r1.x * l2.x + r1.y * l2.y + r1.z * l2.z + r1.w * l2.w);
        int t1 = 0; float best1 = b0;
        if (b1 > best1) { best1 = b1; t1 = 1; }
        if (b2 > best1) { best1 = b2; t1 = 2; }

        sth4_cs(rel_e + (size_t)e0 * D + d0, r0);
        if (has1) sth4_cs(rel_e + (size_t)e1 * D + d0, r1);

        if (l16 == 0) {
            atomicAdd(cnt + (size_t)u0 * NF + t0, 1.0f);
            atomicAdd(cnti + i0, 1.0f);
            rtype[e0] = (unsigned char)t0;
            if (has1) {
                atomicAdd(cnt + (size_t)u1 * NF + t1, 1.0f);
                atomicAdd(cnti + i1, 1.0f);
                rtype[e1] = (unsigned char)t1;
            }
        }
    }
}

// ---------------- scat_u: s1[u,t] += ie16[i]  (8 lanes/edge, LDG.128) ----------------
__global__ __launch_bounds__(256) void scat_u(
    const int* __restrict__ uidx, const int* __restrict__ iidx,
    const unsigned char* __restrict__ rtype,
    const __half* __restrict__ ie16, float* __restrict__ s1, int E)
{
    int g  = (blockIdx.x * blockDim.x + threadIdx.x) >> 3;
    int l8 = threadIdx.x & 7;
    int ng = (gridDim.x * blockDim.x) >> 3;
    int d0 = l8 * 8;

    for (int e0 = g * 2; e0 < E; e0 += ng * 2) {
        int e1 = e0 + 1;
        bool has1 = (e1 < E);
        int u0 = __ldcs(uidx + e0), i0 = __ldcs(iidx + e0);
        int t0 = __ldcs(rtype + e0);
        int u1 = has1 ? __ldcs(uidx + e1) : u0;
        int i1 = has1 ? __ldcs(iidx + e1) : i0;
        int t1 = has1 ? __ldcs(rtype + e1) : t0;

        F8 ie0 = ldh8(ie16 + (size_t)i0 * D + d0);
        F8 ie1 = ldh8(ie16 + (size_t)i1 * D + d0);

        red8(s1 + ((size_t)u0 * NF + t0) * D + d0, ie0);
        if (has1) red8(s1 + ((size_t)u1 * NF + t1) * D + d0, ie1);
    }
}

// ---------------- scat_i: ysum[i] += ue16[u]  (8 lanes/edge) ----------------
__global__ __launch_bounds__(256) void scat_i(
    const int* __restrict__ uidx, const int* __restrict__ iidx,
    const __half* __restrict__ ue16, float* __restrict__ ysum, int E)
{
    int g  = (blockIdx.x * blockDim.x + threadIdx.x) >> 3;
    int l8 = threadIdx.x & 7;
    int ng = (gridDim.x * blockDim.x) >> 3;
    int d0 = l8 * 8;

    for (int e0 = g * 2; e0 < E; e0 += ng * 2) {
        int e1 = e0 + 1;
        bool has1 = (e1 < E);
        int u0 = __ldcs(uidx + e0), i0 = __ldcs(iidx + e0);
        int u1 = has1 ? __ldcs(uidx + e1) : u0;
        int i1 = has1 ? __ldcs(iidx + e1) : i0;

        F8 ue0 = ldh8(ue16 + (size_t)u0 * D + d0);
        F8 ue1 = ldh8(ue16 + (size_t)u1 * D + d0);

        red8(ysum + (size_t)i0 * D + d0, ue0);
        if (has1) red8(ysum + (size_t)i1 * D + d0, ue1);
    }
}

// ---------------- normalize: fp32 sums -> fp16 means ----------------
__global__ __launch_bounds__(256) void normalize16(
    const float* __restrict__ s1, const float* __restrict__ cnt,
    const float* __restrict__ ysum, const float* __restrict__ cnti,
    __half* __restrict__ s1m16, __half* __restrict__ ysm16,
    long q1, long q2)   // quads: q1 = U*NF*D/4, q2 = ENT*D/4
{
    long idx = blockIdx.x * (long)blockDim.x + threadIdx.x;
    long total = q1 + q2;
    long stride = (long)gridDim.x * blockDim.x;
    for (; idx < total; idx += stride) {
        if (idx < q1) {
            float inv = 1.0f / fmaxf(__ldg(cnt + (idx >> 4)), 1.0f);
            float4 v = __ldcs((const float4*)s1 + idx);
            v.x *= inv; v.y *= inv; v.z *= inv; v.w *= inv;
            sth4(s1m16 + idx * 4, v);
        } else {
            long j = idx - q1;
            float inv = 1.0f / fmaxf(__ldg(cnti + (j >> 4)), 1.0f);
            float4 v = __ldcs((const float4*)ysum + j);
            v.x *= inv; v.y *= inv; v.z *= inv; v.w *= inv;
            sth4(ysm16 + j * 4, v);
        }
    }
}

// ---------------- pass2u: sim-weighted user scatter (8 lanes/edge) ----------------
__global__ __launch_bounds__(256) void pass2u(
    const int* __restrict__ uidx, const int* __restrict__ iidx,
    const unsigned char* __restrict__ rtype,
    const __half* __restrict__ rel_e, const __half* __restrict__ s1m16,
    const __half* __restrict__ ie16, float* __restrict__ u2, int E)
{
    int g  = (blockIdx.x * blockDim.x + threadIdx.x) >> 3;
    int l8 = threadIdx.x & 7;
    int ng = (gridDim.x * blockDim.x) >> 3;
    int d0 = l8 * 8;

    for (int e0 = g * 2; e0 < E; e0 += ng * 2) {
        int e1 = e0 + 1;
        bool has1 = (e1 < E);
        int u0 = __ldcs(uidx + e0), i0 = __ldcs(iidx + e0);
        int t0 = __ldcs(rtype + e0);
        int u1 = has1 ? __ldcs(uidx + e1) : u0;
        int i1 = has1 ? __ldcs(iidx + e1) : i0;
        int t1 = has1 ? __ldcs(rtype + e1) : t0;

        F8 r0  = ldh8_cs(rel_e + (size_t)e0 * D + d0);
        F8 um0 = ldh8(s1m16 + ((size_t)u0 * NF + t0) * D + d0);
        F8 ie0 = ldh8(ie16 + (size_t)i0 * D + d0);
        F8 r1  = ldh8_cs(rel_e + (size_t)(has1 ? e1 : e0) * D + d0);
        F8 um1 = ldh8(s1m16 + ((size_t)u1 * NF + t1) * D + d0);
        F8 ie1 = ldh8(ie16 + (size_t)i1 * D + d0);

        float sim0 = hsum8(dot8(r0, um0));
        red8(u2 + ((size_t)u0 * NF + t0) * D + d0, scale8(ie0, sim0));
        if (has1) {
            float sim1 = hsum8(dot8(r1, um1));
            red8(u2 + ((size_t)u1 * NF + t1) * D + d0, scale8(ie1, sim1));
        }
    }
}

// ---------------- pass2i: sim-weighted entity scatter (8 lanes/edge) ----------------
__global__ __launch_bounds__(256) void pass2i(
    const int* __restrict__ uidx, const int* __restrict__ iidx,
    const float* __restrict__ WWi_b,
    const __half* __restrict__ Qu, const __half* __restrict__ Qi,
    const __half* __restrict__ ysm16, const __half* __restrict__ ue16,
    float* __restrict__ y2, int E)
{
    int g  = (blockIdx.x * blockDim.x + threadIdx.x) >> 3;
    int l8 = threadIdx.x & 7;
    int ng = (gridDim.x * blockDim.x) >> 3;
    int d0 = l8 * 8;

    float4 biA = *(const float4*)(WWi_b + d0);
    float4 biB = *(const float4*)(WWi_b + d0 + 4);

    for (int e0 = g * 2; e0 < E; e0 += ng * 2) {
        int e1 = e0 + 1;
        bool has1 = (e1 < E);
        int u0 = __ldcs(uidx + e0), i0 = __ldcs(iidx + e0);
        int u1 = has1 ? __ldcs(uidx + e1) : u0;
        int i1 = has1 ? __ldcs(iidx + e1) : i0;

        F8 qi0 = ldh8(Qi + (size_t)i0 * D + d0);
        F8 qu0 = ldh8(Qu + (size_t)u0 * D + d0);
        F8 ym0 = ldh8(ysm16 + (size_t)i0 * D + d0);
        F8 ue0 = ldh8(ue16 + (size_t)u0 * D + d0);
        F8 qi1 = ldh8(Qi + (size_t)i1 * D + d0);
        F8 qu1 = ldh8(Qu + (size_t)u1 * D + d0);
        F8 ym1 = ldh8(ysm16 + (size_t)i1 * D + d0);
        F8 ue1 = ldh8(ue16 + (size_t)u1 * D + d0);

        F8 rr0;
        rr0.a.x = lrelu(qi0.a.x + qu0.a.x + biA.x);
        rr0.a.y = lrelu(qi0.a.y + qu0.a.y + biA.y);
        rr0.a.z = lrelu(qi0.a.z + qu0.a.z + biA.z);
        rr0.a.w = lrelu(qi0.a.w + qu0.a.w + biA.w);
        rr0.b.x = lrelu(qi0.b.x + qu0.b.x + biB.x);
        rr0.b.y = lrelu(qi0.b.y + qu0.b.y + biB.y);
        rr0.b.z = lrelu(qi0.b.z + qu0.b.z + biB.z);
        rr0.b.w = lrelu(qi0.b.w + qu0.b.w + biB.w);
        float simi0 = hsum8(dot8(rr0, ym0));
        red8(y2 + (size_t)i0 * D + d0, scale8(ue0, simi0));

        if (has1) {
            F8 rr1;
            rr1.a.x = lrelu(qi1.a.x + qu1.a.x + biA.x);
            rr1.a.y = lrelu(qi1.a.y + qu1.a.y + biA.y);
            rr1.a.z = lrelu(qi1.a.z + qu1.a.z + biA.z);
            rr1.a.w = lrelu(qi1.a.w + qu1.a.w + biA.w);
            rr1.b.x = lrelu(qi1.b.x + qu1.b.x + biB.x);
            rr1.b.y = lrelu(qi1.b.y + qu1.b.y + biB.y);
            rr1.b.z = lrelu(qi1.b.z + qu1.b.z + biB.z);
            rr1.b.w = lrelu(qi1.b.w + qu1.b.w + biB.w);
            float simi1 = hsum8(dot8(rr1, ym1));
            red8(y2 + (size_t)i1 * D + d0, scale8(ue1, simi1));
        }
    }
}

// ---------------- K4: squash + residual + combine ----------------
__global__ __launch_bounds__(256) void finalize_entity(
    const float* __restrict__ y2, const float* __restrict__ cnti,
    const float* __restrict__ entity_emb, float* __restrict__ out, int ENT)
{
    int g = blockIdx.x * blockDim.x + threadIdx.x;
    int row = g >> 4;
    int l16 = threadIdx.x & 15;
    int nrows = (gridDim.x * blockDim.x) >> 4;
    int d0 = l16 * 4;
    for (; row < ENT; row += nrows) {
        float inv = 1.0f / fmaxf(cnti[row], 1.0f);
        float4 v = *(const float4*)(y2 + (size_t)row * D + d0);
        v.x *= inv; v.y *= inv; v.z *= inv; v.w *= inv;
        float n2 = hsum16(v.x * v.x + v.y * v.y + v.z * v.z + v.w * v.w);
        float norm = sqrtf(n2);
        float scale = (n2 / (n2 + 1.0f)) / fmaxf(norm, 1e-12f);
        float4 ee = *(const float4*)(entity_emb + (size_t)row * D + d0);
        float4 o;
        o.x = fmaf(scale, v.x, ee.x);
        o.y = fmaf(scale, v.y, ee.y);
        o.z = fmaf(scale, v.z, ee.z);
        o.w = fmaf(scale, v.w, ee.w);
        *(float4*)(out + (size_t)row * D + d0) = o;
    }
}

__global__ __launch_bounds__(256) void finalize_user(
    const float* __restrict__ u2, const float* __restrict__ cnt,
    const float* __restrict__ user_emb, const float* __restrict__ w,
    float* __restrict__ out, int U)
{
    int g = blockIdx.x * blockDim.x + threadIdx.x;
    int row = g >> 4;
    int l16 = threadIdx.x & 15;
    int nrows = (gridDim.x * blockDim.x) >> 4;
    int d0 = l16 * 4;

    float w0 = w[0], w1 = w[1], w2 = w[2];
    float m = fmaxf(w0, fmaxf(w1, w2));
    float e0 = expf(w0 - m), e1 = expf(w1 - m), e2 = expf(w2 - m);
    float inv3 = 1.0f / (e0 + e1 + e2);
    float ws[NF] = {e0 * inv3, e1 * inv3, e2 * inv3};

    for (; row < U; row += nrows) {
        float4 ue = *(const float4*)(user_emb + (size_t)row * D + d0);
        float4 a = make_float4(0.f, 0.f, 0.f, 0.f);
        #pragma unroll
        for (int f = 0; f < NF; f++) {
            float inv = 1.0f / fmaxf(cnt[(size_t)row * NF + f], 1.0f);
            float4 v = *(const float4*)(u2 + ((size_t)row * NF + f) * D + d0);
            v.x *= inv; v.y *= inv; v.z *= inv; v.w *= inv;
            float n2 = hsum16(v.x * v.x + v.y * v.y + v.z * v.z + v.w * v.w);
            float norm = sqrtf(n2);
            float scale = (n2 / (n2 + 1.0f)) / fmaxf(norm, 1e-12f);
            a.x += ws[f] * fmaf(scale, v.x, ue.x);
            a.y += ws[f] * fmaf(scale, v.y, ue.y);
            a.z += ws[f] * fmaf(scale, v.z, ue.z);
            a.w += ws[f] * fmaf(scale, v.w, ue.w);
        }
        *(float4*)(out + (size_t)row * D + d0) = a;
    }
}

// ---------------- host launcher ----------------
extern "C" void kernel_launch(void* const* d_in, const int* in_sizes, int n_in,
                              void* d_out, int out_size)
{
    const float* entity_emb = (const float*)d_in[0];
    const float* user_emb   = (const float*)d_in[1];
    const float* latent     = (const float*)d_in[2];
    const int*   uidx       = (const int*)d_in[3];
    const int*   iidx       = (const int*)d_in[4];
    const float* WW_w       = (const float*)d_in[5];
    const float* WW_b       = (const float*)d_in[6];
    const float* WWi_w      = (const float*)d_in[7];
    const float* WWi_b      = (const float*)d_in[8];
    const float* w          = (const float*)d_in[9];

    int ENT = in_sizes[0] / D;
    int U   = in_sizes[1] / D;
    int E   = in_sizes[3];

    float* out = (float*)d_out;

    float* tabf; __half* tabh; __half* rel; __half* meanp; float* acc; unsigned char* rt;
    cudaGetSymbolAddress((void**)&tabf, g_tabf);
    cudaGetSymbolAddress((void**)&tabh, g_tabh);
    cudaGetSymbolAddress((void**)&rel,  g_rel);
    cudaGetSymbolAddress((void**)&meanp, g_mean);
    cudaGetSymbolAddress((void**)&acc,  g_acc);
    cudaGetSymbolAddress((void**)&rt,   g_rtype);

    float* Pu = tabf;
    float* Pi = Pu + (size_t)U * D;
    __half* Qu   = tabh;
    __half* Qi   = Qu + (size_t)U * D;
    __half* ue16 = Qi + (size_t)ENT * D;
    __half* ie16 = ue16 + (size_t)U * D;
    __half* s1m16 = meanp;
    __half* ysm16 = s1m16 + (size_t)U * NF * D;

    float* s1   = acc;
    float* u2   = s1 + (size_t)U * NF * D;
    float* ys   = u2 + (size_t)U * NF * D;
    float* y2   = ys + (size_t)ENT * D;
    float* cnt  = y2 + (size_t)ENT * D;
    float* cnti = cnt + (size_t)U * NF;
    size_t accN = (size_t)U * NF * D * 2 + (size_t)ENT * D * 2 + (size_t)U * NF + ENT;

    cudaMemsetAsync(acc, 0, accN * sizeof(float));

    precompute2<<<dim3(1024, 2), 256>>>(user_emb, entity_emb, WW_w, WWi_w,
                                        Pu, Pi, Qu, Qi, ue16, ie16, U, ENT);

    int eblocks16 = (E + 31) / 32;   // 16-lane groups, 2 edges each
    int eblocks8  = (E + 63) / 64;   // 8-lane groups, 2 edges each

    route1<<<eblocks16, 256>>>(uidx, iidx, WW_b, latent, Pu, Pi,
                               cnt, cnti, rel, rt, E);

    scat_u<<<eblocks8, 256>>>(uidx, iidx, rt, ie16, s1, E);
    scat_i<<<eblocks8, 256>>>(uidx, iidx, ue16, ys, E);

    long q1 = (long)U * NF * D / 4, q2 = (long)ENT * D / 4;
    normalize16<<<4096, 256>>>(s1, cnt, ys, cnti, s1m16, ysm16, q1, q2);

    pass2u<<<eblocks8, 256>>>(uidx, iidx, rt, rel, s1m16, ie16, u2, E);
    pass2i<<<eblocks8, 256>>>(uidx, iidx, WWi_b, Qu, Qi, ysm16, ue16, y2, E);

    finalize_entity<<<(ENT * 16 + 255) / 256, 256>>>(y2, cnti, entity_emb, out, ENT);
    finalize_user<<<(U * 16 + 255) / 256, 256>>>(u2, cnt, user_emb, w, out + (size_t)ENT * D, U);
}

// round 16
// speedup vs baseline: 1.0174x; 1.0174x over previous
#include <cuda_runtime.h>
#include <cuda_fp16.h>
#include <math.h>

#define D 64
#define NF 3
#define MAXU 100000
#define MAXENT 200000
#define MAXE 500000

typedef unsigned long long ull;

// ---------------- scratch (device globals) ----------------
__device__ __align__(256) float g_tabf[(size_t)(MAXU + MAXENT) * D];          // Pu, Pi (fp32)
__device__ __align__(256) __half g_tabh[(size_t)(MAXU + MAXENT) * 2 * D];     // Qu, Qi, ue16, ie16
__device__ __align__(256) __half g_rel[(size_t)MAXE * D];                     // per-edge rel_ui
__device__ __align__(256) __half g_mean[(size_t)(MAXU * NF + MAXENT) * D];    // s1m16, ysm16
__device__ __align__(256) float g_acc[(size_t)MAXU * NF * D * 2 + (size_t)MAXENT * D * 2
                                      + (size_t)MAXU * NF + MAXENT];
__device__ __align__(256) unsigned char g_rtype[MAXE];

// ---------------- helpers ----------------
__device__ __forceinline__ ull pk2(float a, float b) {
    ull r; asm("mov.b64 %0, {%1, %2};" : "=l"(r) : "f"(a), "f"(b)); return r;
}
__device__ __forceinline__ void fma2(ull& d, ull a, ull b) {
    asm("fma.rn.f32x2 %0, %1, %2, %0;" : "+l"(d) : "l"(a), "l"(b));
}
__device__ __forceinline__ float2 upk2(ull v) {
    float2 f; asm("mov.b64 {%0, %1}, %2;" : "=f"(f.x), "=f"(f.y) : "l"(v)); return f;
}
__device__ __forceinline__ float lrelu(float x) { return x > 0.f ? x : 0.01f * x; }

__device__ __forceinline__ float hsum16(float v) {
    v += __shfl_xor_sync(0xffffffffu, v, 8);
    v += __shfl_xor_sync(0xffffffffu, v, 4);
    v += __shfl_xor_sync(0xffffffffu, v, 2);
    v += __shfl_xor_sync(0xffffffffu, v, 1);
    return v;
}

__device__ __forceinline__ float4 h4_to_f4(uint2 raw) {
    __half2 x = *(__half2*)&raw.x;
    __half2 y = *(__half2*)&raw.y;
    float2 fx = __half22float2(x), fy = __half22float2(y);
    return make_float4(fx.x, fx.y, fy.x, fy.y);
}
__device__ __forceinline__ float4 ldh4(const __half* p)    { return h4_to_f4(*(const uint2*)p); }
__device__ __forceinline__ float4 ldh4_cs(const __half* p) { return h4_to_f4(__ldcs((const uint2*)p)); }
__device__ __forceinline__ uint2 f4_to_h4(float4 v) {
    __half2 h0 = __floats2half2_rn(v.x, v.y);
    __half2 h1 = __floats2half2_rn(v.z, v.w);
    uint2 raw;
    raw.x = *(unsigned int*)&h0;
    raw.y = *(unsigned int*)&h1;
    return raw;
}
__device__ __forceinline__ void sth4(__half* p, float4 v)    { *(uint2*)p = f4_to_h4(v); }
__device__ __forceinline__ void sth4_cs(__half* p, float4 v) { __stcs((uint2*)p, f4_to_h4(v)); }

__device__ __forceinline__ void red4(float* p, float4 v) {
    asm volatile("red.global.add.v4.f32 [%0], {%1, %2, %3, %4};"
                 :: "l"(p), "f"(v.x), "f"(v.y), "f"(v.z), "f"(v.w) : "memory");
}

// ---------------- K0: fused per-source precompute ----------------
__global__ __launch_bounds__(256) void precompute2(
    const float* __restrict__ user_emb, const float* __restrict__ entity_emb,
    const float* __restrict__ WW_w, const float* __restrict__ WWi_w,
    float* __restrict__ Pu, float* __restrict__ Pi,
    __half* __restrict__ Qu, __half* __restrict__ Qi,
    __half* __restrict__ ue16, __half* __restrict__ ie16,
    int U, int ENT)
{
    const int role = blockIdx.y;   // 0 = user, 1 = entity
    const float* src; float* Pdst; __half* Qdst; __half* cp; int rows;
    int colA, colB;
    if (role == 0) { src = user_emb;   Pdst = Pu; Qdst = Qu; cp = ue16; rows = U;
                     colA = 0;  colB = D; }
    else           { src = entity_emb; Pdst = Pi; Qdst = Qi; cp = ie16; rows = ENT;
                     colA = D;  colB = 0; }

    __shared__ float wA[D * D];   // wA[k*64 + d] = WW_w [d][colA + k]
    __shared__ float wB[D * D];   // wB[k*64 + d] = WWi_w[d][colB + k]
    for (int idx = threadIdx.x; idx < D * D; idx += 256) {
        int d = idx >> 6, k = idx & 63;
        wA[k * D + d] = WW_w [d * 2 * D + colA + k];
        wB[k * D + d] = WWi_w[d * 2 * D + colB + k];
    }
    __syncthreads();

    const int hw  = blockIdx.x * 16 + (threadIdx.x >> 4);
    const int nhw = gridDim.x * 16;
    const int l16 = threadIdx.x & 15;
    const int d0  = l16 * 4;

    for (int r = hw; r < rows; r += nhw) {
        float4 x = *(const float4*)(src + (size_t)r * D + d0);
        sth4(cp + (size_t)r * D + d0, x);

        ull aA01 = pk2(0.f, 0.f), aA23 = pk2(0.f, 0.f);
        ull aB01 = pk2(0.f, 0.f), aB23 = pk2(0.f, 0.f);

        #pragma unroll
        for (int j = 0; j < 16; j++) {
            float bx = __shfl_sync(0xffffffffu, x.x, j, 16);
            float by = __shfl_sync(0xffffffffu, x.y, j, 16);
            float bz = __shfl_sync(0xffffffffu, x.z, j, 16);
            float bw = __shfl_sync(0xffffffffu, x.w, j, 16);
            float xv[4] = {bx, by, bz, bw};
            #pragma unroll
            for (int kk = 0; kk < 4; kk++) {
                int k = j * 4 + kk;
                float4 wa = *(const float4*)&wA[k * D + d0];
                float4 wb = *(const float4*)&wB[k * D + d0];
                ull xp = pk2(xv[kk], xv[kk]);
                fma2(aA01, pk2(wa.x, wa.y), xp);
                fma2(aA23, pk2(wa.z, wa.w), xp);
                fma2(aB01, pk2(wb.x, wb.y), xp);
                fma2(aB23, pk2(wb.z, wb.w), xp);
            }
        }

        float2 A01 = upk2(aA01), A23 = upk2(aA23);
        *(float4*)(Pdst + (size_t)r * D + d0)
            = make_float4(A01.x, A01.y, A23.x, A23.y);
        float2 B01 = upk2(aB01), B23 = upk2(aB23);
        sth4(Qdst + (size_t)r * D + d0,
             make_float4(B01.x, B01.y, B23.x, B23.y));
    }
}

// ---------------- K1: fused edge pass 1 — routing + both scatters (16-lane, 2-edge) --
__global__ __launch_bounds__(256) void edge_pass1(
    const int* __restrict__ uidx, const int* __restrict__ iidx,
    const float* __restrict__ WW_b, const float* __restrict__ latent,
    const float* __restrict__ Pu, const float* __restrict__ Pi,
    const __half* __restrict__ ue16, const __half* __restrict__ ie16,
    float* __restrict__ s1, float* __restrict__ cnt,
    float* __restrict__ ysum, float* __restrict__ cnti,
    __half* __restrict__ rel_e, unsigned char* __restrict__ rtype, int E)
{
    int p = (blockIdx.x * blockDim.x + threadIdx.x) >> 4;
    int l16 = threadIdx.x & 15;
    int np = (gridDim.x * blockDim.x) >> 4;
    int d0 = l16 * 4;

    float4 bb = *(const float4*)(WW_b + d0);
    float4 l0 = *(const float4*)(latent + 0 * D + d0);
    float4 l1 = *(const float4*)(latent + 1 * D + d0);
    float4 l2 = *(const float4*)(latent + 2 * D + d0);

    for (int e0 = p * 2; e0 < E; e0 += np * 2) {
        int e1 = e0 + 1;
        bool has1 = (e1 < E);
        int u0 = __ldcs(uidx + e0), i0 = __ldcs(iidx + e0);
        int u1 = has1 ? __ldcs(uidx + e1) : u0;
        int i1 = has1 ? __ldcs(iidx + e1) : i0;

        // ---- all gathers up front (MLP) ----
        float4 pu0 = *(const float4*)(Pu + (size_t)u0 * D + d0);
        float4 pi0 = *(const float4*)(Pi + (size_t)i0 * D + d0);
        float4 pu1 = *(const float4*)(Pu + (size_t)u1 * D + d0);
        float4 pi1 = *(const float4*)(Pi + (size_t)i1 * D + d0);
        float4 ie0 = ldh4(ie16 + (size_t)i0 * D + d0);
        float4 ue0 = ldh4(ue16 + (size_t)u0 * D + d0);
        float4 ie1 = ldh4(ie16 + (size_t)i1 * D + d0);
        float4 ue1 = ldh4(ue16 + (size_t)u1 * D + d0);

        float4 r0;
        r0.x = lrelu(pu0.x + pi0.x + bb.x);
        r0.y = lrelu(pu0.y + pi0.y + bb.y);
        r0.z = lrelu(pu0.z + pi0.z + bb.z);
        r0.w = lrelu(pu0.w + pi0.w + bb.w);
        float a0 = hsum16(r0.x * l0.x + r0.y * l0.y + r0.z * l0.z + r0.w * l0.w);
        float a1 = hsum16(r0.x * l1.x + r0.y * l1.y + r0.z * l1.z + r0.w * l1.w);
        float a2 = hsum16(r0.x * l2.x + r0.y * l2.y + r0.z * l2.z + r0.w * l2.w);
        int t0 = 0; float best0 = a0;
        if (a1 > best0) { best0 = a1; t0 = 1; }
        if (a2 > best0) { best0 = a2; t0 = 2; }

        float4 r1;
        r1.x = lrelu(pu1.x + pi1.x + bb.x);
        r1.y = lrelu(pu1.y + pi1.y + bb.y);
        r1.z = lrelu(pu1.z + pi1.z + bb.z);
        r1.w = lrelu(pu1.w + pi1.w + bb.w);
        float b0 = hsum16(r1.x * l0.x + r1.y * l0.y + r1.z * l0.z + r1.w * l0.w);
        float b1 = hsum16(r1.x * l1.x + r1.y * l1.y + r1.z * l1.z + r1.w * l1.w);
        float b2 = hsum16(r1.x * l2.x + r1.y * l2.y + r1.z * l2.z + r1.w * l2.w);
        int t1 = 0; float best1 = b0;
        if (b1 > best1) { best1 = b1; t1 = 1; }
        if (b2 > best1) { best1 = b2; t1 = 2; }

        sth4_cs(rel_e + (size_t)e0 * D + d0, r0);
        red4(s1 + ((size_t)u0 * NF + t0) * D + d0, ie0);
        red4(ysum + (size_t)i0 * D + d0, ue0);
        if (has1) {
            sth4_cs(rel_e + (size_t)e1 * D + d0, r1);
            red4(s1 + ((size_t)u1 * NF + t1) * D + d0, ie1);
            red4(ysum + (size_t)i1 * D + d0, ue1);
        }
        if (l16 == 0) {
            atomicAdd(cnt + (size_t)u0 * NF + t0, 1.0f);
            atomicAdd(cnti + i0, 1.0f);
            rtype[e0] = (unsigned char)t0;
            if (has1) {
                atomicAdd(cnt + (size_t)u1 * NF + t1, 1.0f);
                atomicAdd(cnti + i1, 1.0f);
                rtype[e1] = (unsigned char)t1;
            }
        }
    }
}

// ---------------- normalize: fp32 sums -> fp16 means ----------------
__global__ __launch_bounds__(256) void normalize16(
    const float* __restrict__ s1, const float* __restrict__ cnt,
    const float* __restrict__ ysum, const float* __restrict__ cnti,
    __half* __restrict__ s1m16, __half* __restrict__ ysm16,
    long q1, long q2)   // quads: q1 = U*NF*D/4, q2 = ENT*D/4
{
    long idx = blockIdx.x * (long)blockDim.x + threadIdx.x;
    long total = q1 + q2;
    long stride = (long)gridDim.x * blockDim.x;
    for (; idx < total; idx += stride) {
        if (idx < q1) {
            float inv = 1.0f / fmaxf(__ldg(cnt + (idx >> 4)), 1.0f);
            float4 v = __ldcs((const float4*)s1 + idx);
            v.x *= inv; v.y *= inv; v.z *= inv; v.w *= inv;
            sth4(s1m16 + idx * 4, v);
        } else {
            long j = idx - q1;
            float inv = 1.0f / fmaxf(__ldg(cnti + (j >> 4)), 1.0f);
            float4 v = __ldcs((const float4*)ysum + j);
            v.x *= inv; v.y *= inv; v.z *= inv; v.w *= inv;
            sth4(ysm16 + j * 4, v);
        }
    }
}

// ---------------- K3: fused edge pass 2 (16-lane, 2-edge, fp16 means) ----------------
__global__ __launch_bounds__(256) void edge_pass2(
    const int* __restrict__ uidx, const int* __restrict__ iidx,
    const float* __restrict__ WWi_b,
    const __half* __restrict__ Qu, const __half* __restrict__ Qi,
    const __half* __restrict__ ue16, const __half* __restrict__ ie16,
    const __half* __restrict__ rel_e, const unsigned char* __restrict__ rtype,
    const __half* __restrict__ s1m16, const __half* __restrict__ ysm16,
    float* __restrict__ u2, float* __restrict__ y2, int E)
{
    int p = (blockIdx.x * blockDim.x + threadIdx.x) >> 4;
    int l16 = threadIdx.x & 15;
    int np = (gridDim.x * blockDim.x) >> 4;
    int d0 = l16 * 4;

    float4 bi = *(const float4*)(WWi_b + d0);

    for (int e0 = p * 2; e0 < E; e0 += np * 2) {
        int e1 = e0 + 1;
        bool has1 = (e1 < E);
        int u0 = __ldcs(uidx + e0), i0 = __ldcs(iidx + e0);
        int t0 = __ldcs(rtype + e0);
        int u1 = has1 ? __ldcs(uidx + e1) : u0;
        int i1 = has1 ? __ldcs(iidx + e1) : i0;
        int t1 = has1 ? __ldcs(rtype + e1) : t0;

        // ---- all gathers up front ----
        float4 r0  = ldh4_cs(rel_e + (size_t)e0 * D + d0);
        float4 um0 = ldh4(s1m16 + ((size_t)u0 * NF + t0) * D + d0);
        float4 ie0 = ldh4(ie16 + (size_t)i0 * D + d0);
        float4 qi0 = ldh4(Qi + (size_t)i0 * D + d0);
        float4 qu0 = ldh4(Qu + (size_t)u0 * D + d0);
        float4 ym0 = ldh4(ysm16 + (size_t)i0 * D + d0);
        float4 ue0 = ldh4(ue16 + (size_t)u0 * D + d0);

        float4 r1  = ldh4_cs(rel_e + (size_t)(has1 ? e1 : e0) * D + d0);
        float4 um1 = ldh4(s1m16 + ((size_t)u1 * NF + t1) * D + d0);
        float4 ie1 = ldh4(ie16 + (size_t)i1 * D + d0);
        float4 qi1 = ldh4(Qi + (size_t)i1 * D + d0);
        float4 qu1 = ldh4(Qu + (size_t)u1 * D + d0);
        float4 ym1 = ldh4(ysm16 + (size_t)i1 * D + d0);
        float4 ue1 = ldh4(ue16 + (size_t)u1 * D + d0);

        // ---- edge 0 ----
        float sim0 = hsum16(r0.x * um0.x + r0.y * um0.y + r0.z * um0.z + r0.w * um0.w);
        red4(u2 + ((size_t)u0 * NF + t0) * D + d0,
             make_float4(sim0 * ie0.x, sim0 * ie0.y, sim0 * ie0.z, sim0 * ie0.w));

        float4 rr0;
        rr0.x = lrelu(qi0.x + qu0.x + bi.x);
        rr0.y = lrelu(qi0.y + qu0.y + bi.y);
        rr0.z = lrelu(qi0.z + qu0.z + bi.z);
        rr0.w = lrelu(qi0.w + qu0.w + bi.w);
        float simi0 = hsum16(rr0.x * ym0.x + rr0.y * ym0.y + rr0.z * ym0.z + rr0.w * ym0.w);
        red4(y2 + (size_t)i0 * D + d0,
             make_float4(simi0 * ue0.x, simi0 * ue0.y, simi0 * ue0.z, simi0 * ue0.w));

        // ---- edge 1 ----
        if (has1) {
            float sim1 = hsum16(r1.x * um1.x + r1.y * um1.y + r1.z * um1.z + r1.w * um1.w);
            red4(u2 + ((size_t)u1 * NF + t1) * D + d0,
                 make_float4(sim1 * ie1.x, sim1 * ie1.y, sim1 * ie1.z, sim1 * ie1.w));

            float4 rr1;
            rr1.x = lrelu(qi1.x + qu1.x + bi.x);
            rr1.y = lrelu(qi1.y + qu1.y + bi.y);
            rr1.z = lrelu(qi1.z + qu1.z + bi.z);
            rr1.w = lrelu(qi1.w + qu1.w + bi.w);
            float simi1 = hsum16(rr1.x * ym1.x + rr1.y * ym1.y + rr1.z * ym1.z + rr1.w * ym1.w);
            red4(y2 + (size_t)i1 * D + d0,
                 make_float4(simi1 * ue1.x, simi1 * ue1.y, simi1 * ue1.z, simi1 * ue1.w));
        }
    }
}

// ---------------- K4: squash + residual + combine ----------------
__global__ __launch_bounds__(256) void finalize_entity(
    const float* __restrict__ y2, const float* __restrict__ cnti,
    const float* __restrict__ entity_emb, float* __restrict__ out, int ENT)
{
    int g = blockIdx.x * blockDim.x + threadIdx.x;
    int row = g >> 4;
    int l16 = threadIdx.x & 15;
    int nrows = (gridDim.x * blockDim.x) >> 4;
    int d0 = l16 * 4;
    for (; row < ENT; row += nrows) {
        float inv = 1.0f / fmaxf(cnti[row], 1.0f);
        float4 v = *(const float4*)(y2 + (size_t)row * D + d0);
        v.x *= inv; v.y *= inv; v.z *= inv; v.w *= inv;
        float n2 = hsum16(v.x * v.x + v.y * v.y + v.z * v.z + v.w * v.w);
        float norm = sqrtf(n2);
        float scale = (n2 / (n2 + 1.0f)) / fmaxf(norm, 1e-12f);
        float4 ee = *(const float4*)(entity_emb + (size_t)row * D + d0);
        float4 o;
        o.x = fmaf(scale, v.x, ee.x);
        o.y = fmaf(scale, v.y, ee.y);
        o.z = fmaf(scale, v.z, ee.z);
        o.w = fmaf(scale, v.w, ee.w);
        *(float4*)(out + (size_t)row * D + d0) = o;
    }
}

__global__ __launch_bounds__(256) void finalize_user(
    const float* __restrict__ u2, const float* __restrict__ cnt,
    const float* __restrict__ user_emb, const float* __restrict__ w,
    float* __restrict__ out, int U)
{
    int g = blockIdx.x * blockDim.x + threadIdx.x;
    int row = g >> 4;
    int l16 = threadIdx.x & 15;
    int nrows = (gridDim.x * blockDim.x) >> 4;
    int d0 = l16 * 4;

    float w0 = w[0], w1 = w[1], w2 = w[2];
    float m = fmaxf(w0, fmaxf(w1, w2));
    float e0 = expf(w0 - m), e1 = expf(w1 - m), e2 = expf(w2 - m);
    float inv3 = 1.0f / (e0 + e1 + e2);
    float ws[NF] = {e0 * inv3, e1 * inv3, e2 * inv3};

    for (; row < U; row += nrows) {
        float4 ue = *(const float4*)(user_emb + (size_t)row * D + d0);
        float4 a = make_float4(0.f, 0.f, 0.f, 0.f);
        #pragma unroll
        for (int f = 0; f < NF; f++) {
            float inv = 1.0f / fmaxf(cnt[(size_t)row * NF + f], 1.0f);
            float4 v = *(const float4*)(u2 + ((size_t)row * NF + f) * D + d0);
            v.x *= inv; v.y *= inv; v.z *= inv; v.w *= inv;
            float n2 = hsum16(v.x * v.x + v.y * v.y + v.z * v.z + v.w * v.w);
            float norm = sqrtf(n2);
            float scale = (n2 / (n2 + 1.0f)) / fmaxf(norm, 1e-12f);
            a.x += ws[f] * fmaf(scale, v.x, ue.x);
            a.y += ws[f] * fmaf(scale, v.y, ue.y);
            a.z += ws[f] * fmaf(scale, v.z, ue.z);
            a.w += ws[f] * fmaf(scale, v.w, ue.w);
        }
        *(float4*)(out + (size_t)row * D + d0) = a;
    }
}

// ---------------- host launcher ----------------
extern "C" void kernel_launch(void* const* d_in, const int* in_sizes, int n_in,
                              void* d_out, int out_size)
{
    const float* entity_emb = (const float*)d_in[0];
    const float* user_emb   = (const float*)d_in[1];
    const float* latent     = (const float*)d_in[2];
    const int*   uidx       = (const int*)d_in[3];
    const int*   iidx       = (const int*)d_in[4];
    const float* WW_w       = (const float*)d_in[5];
    const float* WW_b       = (const float*)d_in[6];
    const float* WWi_w      = (const float*)d_in[7];
    const float* WWi_b      = (const float*)d_in[8];
    const float* w          = (const float*)d_in[9];

    int ENT = in_sizes[0] / D;
    int U   = in_sizes[1] / D;
    int E   = in_sizes[3];

    float* out = (float*)d_out;

    float* tabf; __half* tabh; __half* rel; __half* meanp; float* acc; unsigned char* rt;
    cudaGetSymbolAddress((void**)&tabf, g_tabf);
    cudaGetSymbolAddress((void**)&tabh, g_tabh);
    cudaGetSymbolAddress((void**)&rel,  g_rel);
    cudaGetSymbolAddress((void**)&meanp, g_mean);
    cudaGetSymbolAddress((void**)&acc,  g_acc);
    cudaGetSymbolAddress((void**)&rt,   g_rtype);

    float* Pu = tabf;
    float* Pi = Pu + (size_t)U * D;
    __half* Qu   = tabh;
    __half* Qi   = Qu + (size_t)U * D;
    __half* ue16 = Qi + (size_t)ENT * D;
    __half* ie16 = ue16 + (size_t)U * D;
    __half* s1m16 = meanp;
    __half* ysm16 = s1m16 + (size_t)U * NF * D;

    float* s1   = acc;
    float* u2   = s1 + (size_t)U * NF * D;
    float* ys   = u2 + (size_t)U * NF * D;
    float* y2   = ys + (size_t)ENT * D;
    float* cnt  = y2 + (size_t)ENT * D;
    float* cnti = cnt + (size_t)U * NF;
    size_t accN = (size_t)U * NF * D * 2 + (size_t)ENT * D * 2 + (size_t)U * NF + ENT;

    cudaMemsetAsync(acc, 0, accN * sizeof(float));

    precompute2<<<dim3(1024, 2), 256>>>(user_emb, entity_emb, WW_w, WWi_w,
                                        Pu, Pi, Qu, Qi, ue16, ie16, U, ENT);

    int eblocks = (E + 31) / 32;  // 16 half-warps/block × 2 edges each

    edge_pass1<<<eblocks, 256>>>(uidx, iidx, WW_b, latent, Pu, Pi, ue16, ie16,
                                 s1, cnt, ys, cnti, rel, rt, E);

    long q1 = (long)U * NF * D / 4, q2 = (long)ENT * D / 4;
    normalize16<<<4096, 256>>>(s1, cnt, ys, cnti, s1m16, ysm16, q1, q2);

    edge_pass2<<<eblocks, 256>>>(uidx, iidx, WWi_b, Qu, Qi, ue16, ie16, rel, rt,
                                 s1m16, ysm16, u2, y2, E);

    finalize_entity<<<(ENT * 16 + 255) / 256, 256>>>(y2, cnti, entity_emb, out, ENT);
    finalize_user<<<(U * 16 + 255) / 256, 256>>>(u2, cnt, user_emb, w, out + (size_t)ENT * D, U);
}

// round 17
// speedup vs baseline: 1.3640x; 1.3406x over previous
#include <cuda_runtime.h>
#include <cuda_fp16.h>
#include <math.h>

#define D 64
#define NF 3
#define MAXU 100000
#define MAXENT 200000
#define MAXE 500000

typedef unsigned long long ull;

// ---------------- scratch (device globals) ----------------
__device__ __align__(256) float g_tabf[(size_t)(MAXU + MAXENT) * D];          // Pu, Pi (fp32)
__device__ __align__(256) __half g_tabh[(size_t)(MAXU + MAXENT) * 2 * D];     // Qu, Qi, ue16, ie16
__device__ __align__(256) __half g_rel[(size_t)MAXE * D];                     // per-edge rel_ui
__device__ __align__(256) __half g_mean[(size_t)(MAXU * NF + MAXENT) * D];    // s1m16, ysm16
__device__ __align__(256) float g_acc[(size_t)MAXU * NF * D * 2 + (size_t)MAXENT * D * 2
                                      + (size_t)MAXU * NF + MAXENT];
__device__ __align__(256) unsigned char g_rtype[MAXE];

// ---------------- helpers ----------------
__device__ __forceinline__ ull pk2(float a, float b) {
    ull r; asm("mov.b64 %0, {%1, %2};" : "=l"(r) : "f"(a), "f"(b)); return r;
}
__device__ __forceinline__ void fma2(ull& d, ull a, ull b) {
    asm("fma.rn.f32x2 %0, %1, %2, %0;" : "+l"(d) : "l"(a), "l"(b));
}
__device__ __forceinline__ float2 upk2(ull v) {
    float2 f; asm("mov.b64 {%0, %1}, %2;" : "=f"(f.x), "=f"(f.y) : "l"(v)); return f;
}
__device__ __forceinline__ float lrelu(float x) { return x > 0.f ? x : 0.01f * x; }

__device__ __forceinline__ float hsum16(float v) {
    v += __shfl_xor_sync(0xffffffffu, v, 8);
    v += __shfl_xor_sync(0xffffffffu, v, 4);
    v += __shfl_xor_sync(0xffffffffu, v, 2);
    v += __shfl_xor_sync(0xffffffffu, v, 1);
    return v;
}

__device__ __forceinline__ float4 h4_to_f4(uint2 raw) {
    __half2 x = *(__half2*)&raw.x;
    __half2 y = *(__half2*)&raw.y;
    float2 fx = __half22float2(x), fy = __half22float2(y);
    return make_float4(fx.x, fx.y, fy.x, fy.y);
}
__device__ __forceinline__ float4 ldh4(const __half* p)    { return h4_to_f4(*(const uint2*)p); }
__device__ __forceinline__ float4 ldh4_cs(const __half* p) { return h4_to_f4(__ldcs((const uint2*)p)); }
__device__ __forceinline__ uint2 f4_to_h4(float4 v) {
    __half2 h0 = __floats2half2_rn(v.x, v.y);
    __half2 h1 = __floats2half2_rn(v.z, v.w);
    uint2 raw;
    raw.x = *(unsigned int*)&h0;
    raw.y = *(unsigned int*)&h1;
    return raw;
}
__device__ __forceinline__ void sth4(__half* p, float4 v)    { *(uint2*)p = f4_to_h4(v); }
__device__ __forceinline__ void sth4_cs(__half* p, float4 v) { __stcs((uint2*)p, f4_to_h4(v)); }

__device__ __forceinline__ void red4(float* p, float4 v) {
    asm volatile("red.global.add.v4.f32 [%0], {%1, %2, %3, %4};"
                 :: "l"(p), "f"(v.x), "f"(v.y), "f"(v.z), "f"(v.w) : "memory");
}

// ---------------- K0: per-source precompute, 4-row tiling (weight-reuse) ----------------
// Weights staged in shared once per block; each half-warp computes 4 rows per pass so
// each wa/wb LDS.128 is amortized over 4 rows (LDS traffic /4 vs R11 version).
//  src=user:   P[d] = sum_k WW_w [d][k]      x[k]   Q[d] = sum_k WWi_w[d][64+k] x[k]
//  src=entity: P[d] = sum_k WW_w [d][64+k]   x[k]   Q[d] = sum_k WWi_w[d][k]    x[k]
__global__ __launch_bounds__(256) void precompute3(
    const float* __restrict__ user_emb, const float* __restrict__ entity_emb,
    const float* __restrict__ WW_w, const float* __restrict__ WWi_w,
    float* __restrict__ Pu, float* __restrict__ Pi,
    __half* __restrict__ Qu, __half* __restrict__ Qi,
    __half* __restrict__ ue16, __half* __restrict__ ie16,
    int U, int ENT)
{
    const int role = blockIdx.y;   // 0 = user, 1 = entity
    const float* src; float* Pdst; __half* Qdst; __half* cp; int rows;
    int colA, colB;
    if (role == 0) { src = user_emb;   Pdst = Pu; Qdst = Qu; cp = ue16; rows = U;
                     colA = 0;  colB = D; }
    else           { src = entity_emb; Pdst = Pi; Qdst = Qi; cp = ie16; rows = ENT;
                     colA = D;  colB = 0; }

    __shared__ float wA[D * D];   // wA[k*64 + d] = WW_w [d][colA + k]
    __shared__ float wB[D * D];   // wB[k*64 + d] = WWi_w[d][colB + k]
    for (int idx = threadIdx.x; idx < D * D; idx += 256) {
        int d = idx >> 6, k = idx & 63;
        wA[k * D + d] = WW_w [d * 2 * D + colA + k];
        wB[k * D + d] = WWi_w[d * 2 * D + colB + k];
    }
    __syncthreads();

    const int hw  = blockIdx.x * 16 + (threadIdx.x >> 4);
    const int nhw = gridDim.x * 16;
    const int l16 = threadIdx.x & 15;
    const int d0  = l16 * 4;

    for (long r0 = (long)hw * 4; r0 < rows; r0 += (long)nhw * 4) {
        // ---- load 4 rows into registers (this lane's 4 dims of each), fp16 copy ----
        float xr[4][4];
        #pragma unroll
        for (int m = 0; m < 4; m++) {
            long r = r0 + m;
            float4 v = make_float4(0.f, 0.f, 0.f, 0.f);
            if (r < rows) {
                v = *(const float4*)(src + r * D + d0);
                sth4(cp + r * D + d0, v);
            }
            xr[m][0] = v.x; xr[m][1] = v.y; xr[m][2] = v.z; xr[m][3] = v.w;
        }

        ull aA01[4], aA23[4], aB01[4], aB23[4];
        #pragma unroll
        for (int m = 0; m < 4; m++) {
            aA01[m] = pk2(0.f, 0.f); aA23[m] = pk2(0.f, 0.f);
            aB01[m] = pk2(0.f, 0.f); aB23[m] = pk2(0.f, 0.f);
        }

        #pragma unroll
        for (int j = 0; j < 16; j++) {
            #pragma unroll
            for (int kk = 0; kk < 4; kk++) {
                int k = j * 4 + kk;
                float4 wa = *(const float4*)&wA[k * D + d0];
                float4 wb = *(const float4*)&wB[k * D + d0];
                ull wa01 = pk2(wa.x, wa.y), wa23 = pk2(wa.z, wa.w);
                ull wb01 = pk2(wb.x, wb.y), wb23 = pk2(wb.z, wb.w);
                #pragma unroll
                for (int m = 0; m < 4; m++) {
                    float xv = __shfl_sync(0xffffffffu, xr[m][kk], j, 16);
                    ull xp = pk2(xv, xv);
                    fma2(aA01[m], wa01, xp);
                    fma2(aA23[m], wa23, xp);
                    fma2(aB01[m], wb01, xp);
                    fma2(aB23[m], wb23, xp);
                }
            }
        }

        #pragma unroll
        for (int m = 0; m < 4; m++) {
            long r = r0 + m;
            if (r < rows) {
                float2 A01 = upk2(aA01[m]), A23 = upk2(aA23[m]);
                *(float4*)(Pdst + r * D + d0)
                    = make_float4(A01.x, A01.y, A23.x, A23.y);
                float2 B01 = upk2(aB01[m]), B23 = upk2(aB23[m]);
                sth4(Qdst + r * D + d0,
                     make_float4(B01.x, B01.y, B23.x, B23.y));
            }
        }
    }
}

// ---------------- K1: fused edge pass 1 — routing + both scatters (16-lane, 2-edge) --
__global__ __launch_bounds__(256) void edge_pass1(
    const int* __restrict__ uidx, const int* __restrict__ iidx,
    const float* __restrict__ WW_b, const float* __restrict__ latent,
    const float* __restrict__ Pu, const float* __restrict__ Pi,
    const __half* __restrict__ ue16, const __half* __restrict__ ie16,
    float* __restrict__ s1, float* __restrict__ cnt,
    float* __restrict__ ysum, float* __restrict__ cnti,
    __half* __restrict__ rel_e, unsigned char* __restrict__ rtype, int E)
{
    int p = (blockIdx.x * blockDim.x + threadIdx.x) >> 4;
    int l16 = threadIdx.x & 15;
    int np = (gridDim.x * blockDim.x) >> 4;
    int d0 = l16 * 4;

    float4 bb = *(const float4*)(WW_b + d0);
    float4 l0 = *(const float4*)(latent + 0 * D + d0);
    float4 l1 = *(const float4*)(latent + 1 * D + d0);
    float4 l2 = *(const float4*)(latent + 2 * D + d0);

    for (int e0 = p * 2; e0 < E; e0 += np * 2) {
        int e1 = e0 + 1;
        bool has1 = (e1 < E);
        int u0 = __ldcs(uidx + e0), i0 = __ldcs(iidx + e0);
        int u1 = has1 ? __ldcs(uidx + e1) : u0;
        int i1 = has1 ? __ldcs(iidx + e1) : i0;

        // ---- all gathers up front (MLP) ----
        float4 pu0 = *(const float4*)(Pu + (size_t)u0 * D + d0);
        float4 pi0 = *(const float4*)(Pi + (size_t)i0 * D + d0);
        float4 pu1 = *(const float4*)(Pu + (size_t)u1 * D + d0);
        float4 pi1 = *(const float4*)(Pi + (size_t)i1 * D + d0);
        float4 ie0 = ldh4(ie16 + (size_t)i0 * D + d0);
        float4 ue0 = ldh4(ue16 + (size_t)u0 * D + d0);
        float4 ie1 = ldh4(ie16 + (size_t)i1 * D + d0);
        float4 ue1 = ldh4(ue16 + (size_t)u1 * D + d0);

        float4 r0;
        r0.x = lrelu(pu0.x + pi0.x + bb.x);
        r0.y = lrelu(pu0.y + pi0.y + bb.y);
        r0.z = lrelu(pu0.z + pi0.z + bb.z);
        r0.w = lrelu(pu0.w + pi0.w + bb.w);
        float a0 = hsum16(r0.x * l0.x + r0.y * l0.y + r0.z * l0.z + r0.w * l0.w);
        float a1 = hsum16(r0.x * l1.x + r0.y * l1.y + r0.z * l1.z + r0.w * l1.w);
        float a2 = hsum16(r0.x * l2.x + r0.y * l2.y + r0.z * l2.z + r0.w * l2.w);
        int t0 = 0; float best0 = a0;
        if (a1 > best0) { best0 = a1; t0 = 1; }
        if (a2 > best0) { best0 = a2; t0 = 2; }

        float4 r1;
        r1.x = lrelu(pu1.x + pi1.x + bb.x);
        r1.y = lrelu(pu1.y + pi1.y + bb.y);
        r1.z = lrelu(pu1.z + pi1.z + bb.z);
        r1.w = lrelu(pu1.w + pi1.w + bb.w);
        float b0 = hsum16(r1.x * l0.x + r1.y * l0.y + r1.z * l0.z + r1.w * l0.w);
        float b1 = hsum16(r1.x * l1.x + r1.y * l1.y + r1.z * l1.z + r1.w * l1.w);
        float b2 = hsum16(r1.x * l2.x + r1.y * l2.y + r1.z * l2.z + r1.w * l2.w);
        int t1 = 0; float best1 = b0;
        if (b1 > best1) { best1 = b1; t1 = 1; }
        if (b2 > best1) { best1 = b2; t1 = 2; }

        sth4_cs(rel_e + (size_t)e0 * D + d0, r0);
        red4(s1 + ((size_t)u0 * NF + t0) * D + d0, ie0);
        red4(ysum + (size_t)i0 * D + d0, ue0);
        if (has1) {
            sth4_cs(rel_e + (size_t)e1 * D + d0, r1);
            red4(s1 + ((size_t)u1 * NF + t1) * D + d0, ie1);
            red4(ysum + (size_t)i1 * D + d0, ue1);
        }
        if (l16 == 0) {
            atomicAdd(cnt + (size_t)u0 * NF + t0, 1.0f);
            atomicAdd(cnti + i0, 1.0f);
            rtype[e0] = (unsigned char)t0;
            if (has1) {
                atomicAdd(cnt + (size_t)u1 * NF + t1, 1.0f);
                atomicAdd(cnti + i1, 1.0f);
                rtype[e1] = (unsigned char)t1;
            }
        }
    }
}

// ---------------- normalize: fp32 sums -> fp16 means ----------------
__global__ __launch_bounds__(256) void normalize16(
    const float* __restrict__ s1, const float* __restrict__ cnt,
    const float* __restrict__ ysum, const float* __restrict__ cnti,
    __half* __restrict__ s1m16, __half* __restrict__ ysm16,
    long q1, long q2)   // quads: q1 = U*NF*D/4, q2 = ENT*D/4
{
    long idx = blockIdx.x * (long)blockDim.x + threadIdx.x;
    long total = q1 + q2;
    long stride = (long)gridDim.x * blockDim.x;
    for (; idx < total; idx += stride) {
        if (idx < q1) {
            float inv = 1.0f / fmaxf(__ldg(cnt + (idx >> 4)), 1.0f);
            float4 v = __ldcs((const float4*)s1 + idx);
            v.x *= inv; v.y *= inv; v.z *= inv; v.w *= inv;
            sth4(s1m16 + idx * 4, v);
        } else {
            long j = idx - q1;
            float inv = 1.0f / fmaxf(__ldg(cnti + (j >> 4)), 1.0f);
            float4 v = __ldcs((const float4*)ysum + j);
            v.x *= inv; v.y *= inv; v.z *= inv; v.w *= inv;
            sth4(ysm16 + j * 4, v);
        }
    }
}

// ---------------- K3: fused edge pass 2 (16-lane, 2-edge, fp16 means) ----------------
__global__ __launch_bounds__(256) void edge_pass2(
    const int* __restrict__ uidx, const int* __restrict__ iidx,
    const float* __restrict__ WWi_b,
    const __half* __restrict__ Qu, const __half* __restrict__ Qi,
    const __half* __restrict__ ue16, const __half* __restrict__ ie16,
    const __half* __restrict__ rel_e, const unsigned char* __restrict__ rtype,
    const __half* __restrict__ s1m16, const __half* __restrict__ ysm16,
    float* __restrict__ u2, float* __restrict__ y2, int E)
{
    int p = (blockIdx.x * blockDim.x + threadIdx.x) >> 4;
    int l16 = threadIdx.x & 15;
    int np = (gridDim.x * blockDim.x) >> 4;
    int d0 = l16 * 4;

    float4 bi = *(const float4*)(WWi_b + d0);

    for (int e0 = p * 2; e0 < E; e0 += np * 2) {
        int e1 = e0 + 1;
        bool has1 = (e1 < E);
        int u0 = __ldcs(uidx + e0), i0 = __ldcs(iidx + e0);
        int t0 = __ldcs(rtype + e0);
        int u1 = has1 ? __ldcs(uidx + e1) : u0;
        int i1 = has1 ? __ldcs(iidx + e1) : i0;
        int t1 = has1 ? __ldcs(rtype + e1) : t0;

        // ---- all gathers up front ----
        float4 r0  = ldh4_cs(rel_e + (size_t)e0 * D + d0);
        float4 um0 = ldh4(s1m16 + ((size_t)u0 * NF + t0) * D + d0);
        float4 ie0 = ldh4(ie16 + (size_t)i0 * D + d0);
        float4 qi0 = ldh4(Qi + (size_t)i0 * D + d0);
        float4 qu0 = ldh4(Qu + (size_t)u0 * D + d0);
        float4 ym0 = ldh4(ysm16 + (size_t)i0 * D + d0);
        float4 ue0 = ldh4(ue16 + (size_t)u0 * D + d0);

        float4 r1  = ldh4_cs(rel_e + (size_t)(has1 ? e1 : e0) * D + d0);
        float4 um1 = ldh4(s1m16 + ((size_t)u1 * NF + t1) * D + d0);
        float4 ie1 = ldh4(ie16 + (size_t)i1 * D + d0);
        float4 qi1 = ldh4(Qi + (size_t)i1 * D + d0);
        float4 qu1 = ldh4(Qu + (size_t)u1 * D + d0);
        float4 ym1 = ldh4(ysm16 + (size_t)i1 * D + d0);
        float4 ue1 = ldh4(ue16 + (size_t)u1 * D + d0);

        // ---- edge 0 ----
        float sim0 = hsum16(r0.x * um0.x + r0.y * um0.y + r0.z * um0.z + r0.w * um0.w);
        red4(u2 + ((size_t)u0 * NF + t0) * D + d0,
             make_float4(sim0 * ie0.x, sim0 * ie0.y, sim0 * ie0.z, sim0 * ie0.w));

        float4 rr0;
        rr0.x = lrelu(qi0.x + qu0.x + bi.x);
        rr0.y = lrelu(qi0.y + qu0.y + bi.y);
        rr0.z = lrelu(qi0.z + qu0.z + bi.z);
        rr0.w = lrelu(qi0.w + qu0.w + bi.w);
        float simi0 = hsum16(rr0.x * ym0.x + rr0.y * ym0.y + rr0.z * ym0.z + rr0.w * ym0.w);
        red4(y2 + (size_t)i0 * D + d0,
             make_float4(simi0 * ue0.x, simi0 * ue0.y, simi0 * ue0.z, simi0 * ue0.w));

        // ---- edge 1 ----
        if (has1) {
            float sim1 = hsum16(r1.x * um1.x + r1.y * um1.y + r1.z * um1.z + r1.w * um1.w);
            red4(u2 + ((size_t)u1 * NF + t1) * D + d0,
                 make_float4(sim1 * ie1.x, sim1 * ie1.y, sim1 * ie1.z, sim1 * ie1.w));

            float4 rr1;
            rr1.x = lrelu(qi1.x + qu1.x + bi.x);
            rr1.y = lrelu(qi1.y + qu1.y + bi.y);
            rr1.z = lrelu(qi1.z + qu1.z + bi.z);
            rr1.w = lrelu(qi1.w + qu1.w + bi.w);
            float simi1 = hsum16(rr1.x * ym1.x + rr1.y * ym1.y + rr1.z * ym1.z + rr1.w * ym1.w);
            red4(y2 + (size_t)i1 * D + d0,
                 make_float4(simi1 * ue1.x, simi1 * ue1.y, simi1 * ue1.z, simi1 * ue1.w));
        }
    }
}

// ---------------- K4: squash + residual + combine ----------------
__global__ __launch_bounds__(256) void finalize_entity(
    const float* __restrict__ y2, const float* __restrict__ cnti,
    const float* __restrict__ entity_emb, float* __restrict__ out, int ENT)
{
    int g = blockIdx.x * blockDim.x + threadIdx.x;
    int row = g >> 4;
    int l16 = threadIdx.x & 15;
    int nrows = (gridDim.x * blockDim.x) >> 4;
    int d0 = l16 * 4;
    for (; row < ENT; row += nrows) {
        float inv = 1.0f / fmaxf(cnti[row], 1.0f);
        float4 v = *(const float4*)(y2 + (size_t)row * D + d0);
        v.x *= inv; v.y *= inv; v.z *= inv; v.w *= inv;
        float n2 = hsum16(v.x * v.x + v.y * v.y + v.z * v.z + v.w * v.w);
        float norm = sqrtf(n2);
        float scale = (n2 / (n2 + 1.0f)) / fmaxf(norm, 1e-12f);
        float4 ee = *(const float4*)(entity_emb + (size_t)row * D + d0);
        float4 o;
        o.x = fmaf(scale, v.x, ee.x);
        o.y = fmaf(scale, v.y, ee.y);
        o.z = fmaf(scale, v.z, ee.z);
        o.w = fmaf(scale, v.w, ee.w);
        *(float4*)(out + (size_t)row * D + d0) = o;
    }
}

__global__ __launch_bounds__(256) void finalize_user(
    const float* __restrict__ u2, const float* __restrict__ cnt,
    const float* __restrict__ user_emb, const float* __restrict__ w,
    float* __restrict__ out, int U)
{
    int g = blockIdx.x * blockDim.x + threadIdx.x;
    int row = g >> 4;
    int l16 = threadIdx.x & 15;
    int nrows = (gridDim.x * blockDim.x) >> 4;
    int d0 = l16 * 4;

    float w0 = w[0], w1 = w[1], w2 = w[2];
    float m = fmaxf(w0, fmaxf(w1, w2));
    float e0 = expf(w0 - m), e1 = expf(w1 - m), e2 = expf(w2 - m);
    float inv3 = 1.0f / (e0 + e1 + e2);
    float ws[NF] = {e0 * inv3, e1 * inv3, e2 * inv3};

    for (; row < U; row += nrows) {
        float4 ue = *(const float4*)(user_emb + (size_t)row * D + d0);
        float4 a = make_float4(0.f, 0.f, 0.f, 0.f);
        #pragma unroll
        for (int f = 0; f < NF; f++) {
            float inv = 1.0f / fmaxf(cnt[(size_t)row * NF + f], 1.0f);
            float4 v = *(const float4*)(u2 + ((size_t)row * NF + f) * D + d0);
            v.x *= inv; v.y *= inv; v.z *= inv; v.w *= inv;
            float n2 = hsum16(v.x * v.x + v.y * v.y + v.z * v.z + v.w * v.w);
            float norm = sqrtf(n2);
            float scale = (n2 / (n2 + 1.0f)) / fmaxf(norm, 1e-12f);
            a.x += ws[f] * fmaf(scale, v.x, ue.x);
            a.y += ws[f] * fmaf(scale, v.y, ue.y);
            a.z += ws[f] * fmaf(scale, v.z, ue.z);
            a.w += ws[f] * fmaf(scale, v.w, ue.w);
        }
        *(float4*)(out + (size_t)row * D + d0) = a;
    }
}

// ---------------- host launcher ----------------
extern "C" void kernel_launch(void* const* d_in, const int* in_sizes, int n_in,
                              void* d_out, int out_size)
{
    const float* entity_emb = (const float*)d_in[0];
    const float* user_emb   = (const float*)d_in[1];
    const float* latent     = (const float*)d_in[2];
    const int*   uidx       = (const int*)d_in[3];
    const int*   iidx       = (const int*)d_in[4];
    const float* WW_w       = (const float*)d_in[5];
    const float* WW_b       = (const float*)d_in[6];
    const float* WWi_w      = (const float*)d_in[7];
    const float* WWi_b      = (const float*)d_in[8];
    const float* w          = (const float*)d_in[9];

    int ENT = in_sizes[0] / D;
    int U   = in_sizes[1] / D;
    int E   = in_sizes[3];

    float* out = (float*)d_out;

    float* tabf; __half* tabh; __half* rel; __half* meanp; float* acc; unsigned char* rt;
    cudaGetSymbolAddress((void**)&tabf, g_tabf);
    cudaGetSymbolAddress((void**)&tabh, g_tabh);
    cudaGetSymbolAddress((void**)&rel,  g_rel);
    cudaGetSymbolAddress((void**)&meanp, g_mean);
    cudaGetSymbolAddress((void**)&acc,  g_acc);
    cudaGetSymbolAddress((void**)&rt,   g_rtype);

    float* Pu = tabf;
    float* Pi = Pu + (size_t)U * D;
    __half* Qu   = tabh;
    __half* Qi   = Qu + (size_t)U * D;
    __half* ue16 = Qi + (size_t)ENT * D;
    __half* ie16 = ue16 + (size_t)U * D;
    __half* s1m16 = meanp;
    __half* ysm16 = s1m16 + (size_t)U * NF * D;

    float* s1   = acc;
    float* u2   = s1 + (size_t)U * NF * D;
    float* ys   = u2 + (size_t)U * NF * D;
    float* y2   = ys + (size_t)ENT * D;
    float* cnt  = y2 + (size_t)ENT * D;
    float* cnti = cnt + (size_t)U * NF;
    size_t accN = (size_t)U * NF * D * 2 + (size_t)ENT * D * 2 + (size_t)U * NF + ENT;

    cudaMemsetAsync(acc, 0, accN * sizeof(float));

    precompute3<<<dim3(1024, 2), 256>>>(user_emb, entity_emb, WW_w, WWi_w,
                                        Pu, Pi, Qu, Qi, ue16, ie16, U, ENT);

    int eblocks = (E + 31) / 32;  // 16 half-warps/block × 2 edges each

    edge_pass1<<<eblocks, 256>>>(uidx, iidx, WW_b, latent, Pu, Pi, ue16, ie16,
                                 s1, cnt, ys, cnti, rel, rt, E);

    long q1 = (long)U * NF * D / 4, q2 = (long)ENT * D / 4;
    normalize16<<<4096, 256>>>(s1, cnt, ys, cnti, s1m16, ysm16, q1, q2);

    edge_pass2<<<eblocks, 256>>>(uidx, iidx, WWi_b, Qu, Qi, ue16, ie16, rel, rt,
                                 s1m16, ysm16, u2, y2, E);

    finalize_entity<<<(ENT * 16 + 255) / 256, 256>>>(y2, cnti, entity_emb, out, ENT);
    finalize_user<<<(U * 16 + 255) / 256, 256>>>(u2, cnt, user_emb, w, out + (size_t)ENT * D, U);
}